// round 6
// baseline (speedup 1.0000x reference)
#include <cuda_runtime.h>
#include <float.h>

#define HH 4
#define BB 1024
#define DQv 512
#define DFv 128
#define DD1 128
#define DD2 64

__device__ float g_Wq[HH * DQv * DD2];
__device__ float g_bq[HH * DD2];
__device__ float g_Wc[HH * DFv * 128];   // [h][k][c] c<64: f, c>=64: v
__device__ float g_bc[HH * 128];
__device__ float g_fq[BB * HH * DD2];

__device__ __forceinline__ void ffma2(unsigned long long& d, unsigned long long a, unsigned long long b) {
    asm("fma.rn.f32x2 %0, %1, %2, %0;" : "+l"(d) : "l"(a), "l"(b));
}
__device__ __forceinline__ unsigned long long dup2(float x) {
    unsigned long long r; unsigned int u = __float_as_uint(x);
    asm("mov.b64 %0, {%1, %1};" : "=l"(r) : "r"(u));
    return r;
}
__device__ __forceinline__ float2 unpk(unsigned long long v) {
    unsigned int lo, hi;
    asm("mov.b64 {%0, %1}, %2;" : "=r"(lo), "=r"(hi) : "l"(v));
    return make_float2(__uint_as_float(lo), __uint_as_float(hi));
}
__device__ __forceinline__ float silu_f(float x) {
    return __fdividef(x, 1.f + __expf(-x));
}

// ---------------- weight collapse (proven) ----------------
__global__ void collapse_q_kernel(const float* __restrict__ Wq1, const float* __restrict__ bq1,
                                  const float* __restrict__ Wq2, const float* __restrict__ bq2) {
    int idx = blockIdx.x * 256 + threadIdx.x;
    int c = idx & 63, k = (idx >> 6) & 511, h = idx >> 15;
    const float* a  = Wq1 + (h * DQv + k) * DD1;
    const float* w2 = Wq2 + h * DD1 * DD2 + c;
    float acc = 0.f;
#pragma unroll 8
    for (int j = 0; j < DD1; ++j) acc += a[j] * w2[j * DD2];
    g_Wq[idx] = acc;
    if (k == 0) {
        float bb = bq2[h * DD2 + c];
        const float* b1p = bq1 + h * DD1;
#pragma unroll 8
        for (int j = 0; j < DD1; ++j) bb += b1p[j] * w2[j * DD2];
        g_bq[h * DD2 + c] = bb;
    }
}

__global__ void collapse_fv_kernel(const float* __restrict__ Wf1, const float* __restrict__ bf1,
                                   const float* __restrict__ Wf2, const float* __restrict__ bf2,
                                   const float* __restrict__ Wv1, const float* __restrict__ bv1,
                                   const float* __restrict__ Wv2, const float* __restrict__ bv2) {
    int idx = blockIdx.x * 256 + threadIdx.x;
    int c = idx & 127, k = (idx >> 7) & 127, h = idx >> 14;
    const float *W1, *W2, *B1, *B2; int cc;
    if (c < 64) { W1 = Wf1; W2 = Wf2; B1 = bf1; B2 = bf2; cc = c; }
    else        { W1 = Wv1; W2 = Wv2; B1 = bv1; B2 = bv2; cc = c - 64; }
    const float* a  = W1 + (h * DFv + k) * DD1;
    const float* w2 = W2 + h * DD1 * DD2 + cc;
    float acc = 0.f;
#pragma unroll 8
    for (int j = 0; j < DD1; ++j) acc += a[j] * w2[j * DD2];
    g_Wc[idx] = acc;
    if (k == 0) {
        float bb = B2[h * DD2 + cc];
        const float* b1p = B1 + h * DD1;
#pragma unroll 8
        for (int j = 0; j < DD1; ++j) bb += b1p[j] * w2[j * DD2];
        g_bc[h * 128 + c] = bb;
    }
}

__global__ __launch_bounds__(256) void fq_kernel(const float* __restrict__ query) {
    __shared__ float qs[32 * 68];
    __shared__ float ws[64 * 64];
    const int tid = threadIdx.x;
    const int h  = blockIdx.x & 3;
    const int bg = blockIdx.x >> 2;
    const int bl = tid >> 3, cg = tid & 7;
    float acc[8];
#pragma unroll
    for (int j = 0; j < 8; ++j) acc[j] = 0.f;
    for (int kc = 0; kc < 8; ++kc) {
        __syncthreads();
#pragma unroll
        for (int it = 0; it < 8; ++it) {
            int idx = tid + it * 256;
            qs[(idx >> 6) * 68 + (idx & 63)] = query[(bg * 32 + (idx >> 6)) * DQv + kc * 64 + (idx & 63)];
        }
#pragma unroll
        for (int it = 0; it < 16; ++it) {
            int idx = tid + it * 256;
            ws[idx] = g_Wq[(h * DQv + kc * 64 + (idx >> 6)) * DD2 + (idx & 63)];
        }
        __syncthreads();
#pragma unroll 4
        for (int k = 0; k < 64; ++k) {
            float qv = qs[bl * 68 + k];
            float4 w01 = *reinterpret_cast<const float4*>(ws + k * 64 + cg * 8);
            float4 w23 = *reinterpret_cast<const float4*>(ws + k * 64 + cg * 8 + 4);
            acc[0] += qv * w01.x; acc[1] += qv * w01.y;
            acc[2] += qv * w01.z; acc[3] += qv * w01.w;
            acc[4] += qv * w23.x; acc[5] += qv * w23.y;
            acc[6] += qv * w23.z; acc[7] += qv * w23.w;
        }
    }
    int bglob = bg * 32 + bl;
#pragma unroll
    for (int j = 0; j < 8; ++j) {
        int c = cg * 8 + j;
        g_fq[bglob * 256 + h * 64 + c] = silu_f(acc[j] + g_bq[h * DD2 + c]);
    }
}

// ---------------- fused main kernel: one block per (b,h), 2 CTAs/SM ----------------
// 8 warps: ch = w&1 (col half, 64 cols), wr = w>>1 (20-row block).
// Lane: rg = lane>>4 -> gg = wr*2+rg (10-row group), cg = lane&15 -> 4 cols.
// 3 passes of 80/80/40 rows. fdT[k][96]: 8 groups x (10 rows + 2 pad), transposed.
#define OFF_FDT  16384
#define OFF_LG   (OFF_FDT + 12288)
#define OFF_MO   (OFF_LG + 80)
#define OFF_MP   (OFF_MO + 512)
#define OFF_MS   (OFF_MP + 512)
#define SMEM_FLOATS (OFF_MS + 16)
#define SMEM_BYTES  (SMEM_FLOATS * 4)

__global__ __launch_bounds__(256, 2) void mha_main_kernel(
    const float* __restrict__ fact,
    const int* __restrict__ mask, const float* __restrict__ mm,
    const float* __restrict__ tau1, const float* __restrict__ tau2,
    float* __restrict__ out)
{
    extern __shared__ float sm[];
    float* W_s  = sm;              // [128 k][128 c]
    float* fdT  = sm + OFF_FDT;    // [128 k][96]
    float* lg_s = sm + OFF_LG;     // [80]
    float* mo   = sm + OFF_MO;     // [8][64]
    float* mp   = sm + OFF_MP;     // [8][64]
    float* mSs  = sm + OFF_MS;     // [16]

    const int tid = threadIdx.x;
    const int b = blockIdx.x >> 2;
    const int h = blockIdx.x & 3;
    const int w    = tid >> 5;
    const int lane = tid & 31;
    const int ch = w & 1;              // 0: f-cols, 1: v-cols
    const int wr = w >> 1;             // 0..3
    const int rg = lane >> 4;
    const int cg = lane & 15;
    const int gg = wr * 2 + rg;        // 0..7 (10 rows each)
    const int col = ch * 64 + cg * 4;  // 4 cols
    const bool is_f = (ch == 0);

    // staging identity
    const int sgg = lane >> 3;         // 0..3
    const int sks = (lane >> 1) & 3;   // 0..3
    const int sjh = lane & 1;          // 0..1

    // stage W
    {
        const float4* gw = reinterpret_cast<const float4*>(g_Wc + h * 16384);
        float4* ws4 = reinterpret_cast<float4*>(W_s);
#pragma unroll
        for (int i = 0; i < 16; ++i) ws4[tid + 256 * i] = gw[tid + 256 * i];
    }

    const float t1a = tau1[h], t1b = tau1[4 + h];
    const float cb1v = tau2[h], cb2v = tau2[4 + h], cb3v = tau2[8 + h];

    float4 bc4 = *reinterpret_cast<const float4*>(g_bc + h * 128 + col);
    float4 fq4 = make_float4(0.f, 0.f, 0.f, 0.f);
    if (is_f) fq4 = *reinterpret_cast<const float4*>(g_fq + b * 256 + h * 64 + col);

    const float4* fact4 = reinterpret_cast<const float4*>(fact + (long)b * 200 * 128);

    float m_run = -FLT_MAX, S_run = 0.f;
    float ov[4] = {0.f, 0.f, 0.f, 0.f}, pv[4] = {0.f, 0.f, 0.f, 0.f};

#pragma unroll 1
    for (int t = 0; t < 3; ++t) {
        const int tb = t * 80;
        __syncthreads();   // fdT(t-1) + lg(t-1) fully consumed
        // ---- stage 80-row transposed tile (zero-pad rows >= 200) ----
        const int kb = 16 * w + 4 * sks;
#pragma unroll
        for (int g2 = 0; g2 < 2; ++g2) {
#pragma unroll
            for (int jj = 0; jj < 5; ++jj) {
                int j5 = jj + sks; if (j5 >= 5) j5 -= 5;
                int j = 5 * sjh + j5;
                int grp = sgg + 4 * g2;
                int lrow = tb + 10 * grp + j;
                float4 f = (lrow < 200) ? fact4[lrow * 32 + 4 * w + sks]
                                        : make_float4(0.f, 0.f, 0.f, 0.f);
                float* d = fdT + 12 * grp + j;
                d[(kb + 0) * 96] = f.x;
                d[(kb + 1) * 96] = f.y;
                d[(kb + 2) * 96] = f.z;
                d[(kb + 3) * 96] = f.w;
            }
        }
        __syncthreads();

        // ---- mainloop: 5 row-pairs x 4 cols per lane ----
        unsigned long long a0[5], a1[5], a2[5], a3[5];
#pragma unroll
        for (int p = 0; p < 5; ++p) { a0[p] = 0ull; a1[p] = 0ull; a2[p] = 0ull; a3[p] = 0ull; }
        {
            const float* ap = fdT + 12 * gg;
            const float* wp = W_s + col;
#pragma unroll 4
            for (int k = 0; k < 128; ++k) {
                ulonglong2 f01 = *reinterpret_cast<const ulonglong2*>(ap);
                ulonglong2 f23 = *reinterpret_cast<const ulonglong2*>(ap + 4);
                unsigned long long f4 = *reinterpret_cast<const unsigned long long*>(ap + 8);
                float4 wv = *reinterpret_cast<const float4*>(wp);
                unsigned long long w0 = dup2(wv.x), w1 = dup2(wv.y);
                unsigned long long w2 = dup2(wv.z), w3 = dup2(wv.w);
                ffma2(a0[0], f01.x, w0); ffma2(a1[0], f01.x, w1); ffma2(a2[0], f01.x, w2); ffma2(a3[0], f01.x, w3);
                ffma2(a0[1], f01.y, w0); ffma2(a1[1], f01.y, w1); ffma2(a2[1], f01.y, w2); ffma2(a3[1], f01.y, w3);
                ffma2(a0[2], f23.x, w0); ffma2(a1[2], f23.x, w1); ffma2(a2[2], f23.x, w2); ffma2(a3[2], f23.x, w3);
                ffma2(a0[3], f23.y, w0); ffma2(a1[3], f23.y, w1); ffma2(a2[3], f23.y, w2); ffma2(a3[3], f23.y, w3);
                ffma2(a0[4], f4,    w0); ffma2(a1[4], f4,    w1); ffma2(a2[4], f4,    w2); ffma2(a3[4], f4,    w3);
                ap += 96; wp += 128;
            }
        }

        // ---- epilogue ----
        float sv[10][4];
#pragma unroll
        for (int p = 0; p < 5; ++p) {
            float2 c0 = unpk(a0[p]), c1 = unpk(a1[p]);
            float2 c2 = unpk(a2[p]), c3 = unpk(a3[p]);
            sv[2*p][0]   = silu_f(c0.x + bc4.x); sv[2*p][1]   = silu_f(c1.x + bc4.y);
            sv[2*p][2]   = silu_f(c2.x + bc4.z); sv[2*p][3]   = silu_f(c3.x + bc4.w);
            sv[2*p+1][0] = silu_f(c0.y + bc4.x); sv[2*p+1][1] = silu_f(c1.y + bc4.y);
            sv[2*p+1][2] = silu_f(c2.y + bc4.z); sv[2*p+1][3] = silu_f(c3.y + bc4.w);
        }
        if (is_f) {
            float pd[10];
#pragma unroll
            for (int j = 0; j < 10; ++j) {
                pd[j] = sv[j][0] * fq4.x + sv[j][1] * fq4.y + sv[j][2] * fq4.z + sv[j][3] * fq4.w;
#pragma unroll
                for (int off = 8; off > 0; off >>= 1)
                    pd[j] += __shfl_xor_sync(0xffffffffu, pd[j], off);
            }
            float mine = pd[0];
#pragma unroll
            for (int j = 1; j < 10; ++j)
                if (cg == j) mine = pd[j];
            int l = tb + gg * 10 + cg;
            if (cg < 10 && l < 200) {
                float mk = (float)mask[b * 200 + l];
                float dd = mine + (-1e9f) * (1.f - mk);   // mask BEFORE cosine mix
                float bias = mm[b * 200 + l] / t1a + mm[204800 + b * 200 + l] / t1b;
                lg_s[gg * 10 + cg] = cb1v * dd + cb2v * bias + cb3v * dd * bias;
            }
        }
        __syncthreads();   // lg_s(t) visible; fdT(t) consumed

        if (!is_f && (t < 2 || gg < 4)) {
#pragma unroll
            for (int j = 0; j < 10; ++j) {
                float lgv = lg_s[gg * 10 + j];
                float mn = fmaxf(m_run, lgv);
                float sc = __expf(m_run - mn);
                float e  = __expf(lgv - mn);
                S_run = S_run * sc + e;
#pragma unroll
                for (int c = 0; c < 4; ++c) {
                    ov[c] = ov[c] * sc + e * sv[j][c];
                    pv[c] += sv[j][c];
                }
                m_run = mn;
            }
        }
    }

    // ---- merge 8 row-groups ----
    if (!is_f) {
        int cv = col - 64;
#pragma unroll
        for (int c = 0; c < 4; ++c) {
            mo[gg * 64 + cv + c] = ov[c];
            mp[gg * 64 + cv + c] = pv[c];
        }
        if (cg == 0) { mSs[gg] = m_run; mSs[8 + gg] = S_run; }
    }
    __syncthreads();

    if (tid < 64) {
        float M = -FLT_MAX;
#pragma unroll
        for (int g = 0; g < 8; ++g) M = fmaxf(M, mSs[g]);
        float S = 0.f, o = 0.f, p = 0.f;
#pragma unroll
        for (int g = 0; g < 8; ++g) {
            float e = __expf(mSs[g] - M);
            S += mSs[8 + g] * e;
            o += mo[g * 64 + tid] * e;
            p += mp[g * 64 + tid];
        }
        out[b * 256 + h * 64 + tid] = o / S + 1e-7f * p;
    }
}

extern "C" void kernel_launch(void* const* d_in, const int* in_sizes, int n_in,
                              void* d_out, int out_size) {
    const float* query = (const float*)d_in[0];
    const float* fact  = (const float*)d_in[1];
    const int*   mask  = (const int*)  d_in[2];
    const float* mm    = (const float*)d_in[3];
    const float* Wq1   = (const float*)d_in[4];
    const float* bq1   = (const float*)d_in[5];
    const float* Wq2   = (const float*)d_in[6];
    const float* bq2   = (const float*)d_in[7];
    const float* Wf1   = (const float*)d_in[8];
    const float* bf1   = (const float*)d_in[9];
    const float* Wf2   = (const float*)d_in[10];
    const float* bf2   = (const float*)d_in[11];
    const float* Wv1   = (const float*)d_in[12];
    const float* bv1   = (const float*)d_in[13];
    const float* Wv2   = (const float*)d_in[14];
    const float* bv2   = (const float*)d_in[15];
    const float* tau1  = (const float*)d_in[16];
    const float* tau2  = (const float*)d_in[17];
    float* out = (float*)d_out;

    cudaFuncSetAttribute(mha_main_kernel, cudaFuncAttributeMaxDynamicSharedMemorySize, SMEM_BYTES);

    collapse_q_kernel<<<512, 256>>>(Wq1, bq1, Wq2, bq2);
    collapse_fv_kernel<<<256, 256>>>(Wf1, bf1, Wf2, bf2, Wv1, bv1, Wv2, bv2);
    fq_kernel<<<128, 256>>>(query);
    mha_main_kernel<<<BB * HH, 256, SMEM_BYTES>>>(fact, mask, mm, tau1, tau2, out);
}

// round 7
// speedup vs baseline: 1.1746x; 1.1746x over previous
#include <cuda_runtime.h>
#include <float.h>

#define HH 4
#define BB 1024
#define DQv 512
#define DFv 128
#define DD1 128
#define DD2 64

__device__ float g_Wq[HH * DQv * DD2];
__device__ float g_bq[HH * DD2];
__device__ float g_Wc[HH * DFv * 128];   // [h][k][c] c<64: f, c>=64: v
__device__ float g_bc[HH * 128];
__device__ float g_fq[BB * HH * DD2];

__device__ __forceinline__ void ffma2(unsigned long long& d, unsigned long long a, unsigned long long b) {
    asm("fma.rn.f32x2 %0, %1, %2, %0;" : "+l"(d) : "l"(a), "l"(b));
}
__device__ __forceinline__ unsigned long long dup2(float x) {
    unsigned long long r; unsigned int u = __float_as_uint(x);
    asm("mov.b64 %0, {%1, %1};" : "=l"(r) : "r"(u));
    return r;
}
__device__ __forceinline__ float2 unpk(unsigned long long v) {
    unsigned int lo, hi;
    asm("mov.b64 {%0, %1}, %2;" : "=r"(lo), "=r"(hi) : "l"(v));
    return make_float2(__uint_as_float(lo), __uint_as_float(hi));
}
__device__ __forceinline__ float silu_f(float x) {
    return __fdividef(x, 1.f + __expf(-x));
}

// ---------------- weight collapse (proven) ----------------
__global__ void collapse_q_kernel(const float* __restrict__ Wq1, const float* __restrict__ bq1,
                                  const float* __restrict__ Wq2, const float* __restrict__ bq2) {
    int idx = blockIdx.x * 256 + threadIdx.x;
    int c = idx & 63, k = (idx >> 6) & 511, h = idx >> 15;
    const float* a  = Wq1 + (h * DQv + k) * DD1;
    const float* w2 = Wq2 + h * DD1 * DD2 + c;
    float acc = 0.f;
#pragma unroll 8
    for (int j = 0; j < DD1; ++j) acc += a[j] * w2[j * DD2];
    g_Wq[idx] = acc;
    if (k == 0) {
        float bb = bq2[h * DD2 + c];
        const float* b1p = bq1 + h * DD1;
#pragma unroll 8
        for (int j = 0; j < DD1; ++j) bb += b1p[j] * w2[j * DD2];
        g_bq[h * DD2 + c] = bb;
    }
}

__global__ void collapse_fv_kernel(const float* __restrict__ Wf1, const float* __restrict__ bf1,
                                   const float* __restrict__ Wf2, const float* __restrict__ bf2,
                                   const float* __restrict__ Wv1, const float* __restrict__ bv1,
                                   const float* __restrict__ Wv2, const float* __restrict__ bv2) {
    int idx = blockIdx.x * 256 + threadIdx.x;
    int c = idx & 127, k = (idx >> 7) & 127, h = idx >> 14;
    const float *W1, *W2, *B1, *B2; int cc;
    if (c < 64) { W1 = Wf1; W2 = Wf2; B1 = bf1; B2 = bf2; cc = c; }
    else        { W1 = Wv1; W2 = Wv2; B1 = bv1; B2 = bv2; cc = c - 64; }
    const float* a  = W1 + (h * DFv + k) * DD1;
    const float* w2 = W2 + h * DD1 * DD2 + cc;
    float acc = 0.f;
#pragma unroll 8
    for (int j = 0; j < DD1; ++j) acc += a[j] * w2[j * DD2];
    g_Wc[idx] = acc;
    if (k == 0) {
        float bb = B2[h * DD2 + cc];
        const float* b1p = B1 + h * DD1;
#pragma unroll 8
        for (int j = 0; j < DD1; ++j) bb += b1p[j] * w2[j * DD2];
        g_bc[h * 128 + c] = bb;
    }
}

__global__ __launch_bounds__(256) void fq_kernel(const float* __restrict__ query) {
    __shared__ float qs[32 * 68];
    __shared__ float ws[64 * 64];
    const int tid = threadIdx.x;
    const int h  = blockIdx.x & 3;
    const int bg = blockIdx.x >> 2;
    const int bl = tid >> 3, cg = tid & 7;
    float acc[8];
#pragma unroll
    for (int j = 0; j < 8; ++j) acc[j] = 0.f;
    for (int kc = 0; kc < 8; ++kc) {
        __syncthreads();
#pragma unroll
        for (int it = 0; it < 8; ++it) {
            int idx = tid + it * 256;
            qs[(idx >> 6) * 68 + (idx & 63)] = query[(bg * 32 + (idx >> 6)) * DQv + kc * 64 + (idx & 63)];
        }
#pragma unroll
        for (int it = 0; it < 16; ++it) {
            int idx = tid + it * 256;
            ws[idx] = g_Wq[(h * DQv + kc * 64 + (idx >> 6)) * DD2 + (idx & 63)];
        }
        __syncthreads();
#pragma unroll 4
        for (int k = 0; k < 64; ++k) {
            float qv = qs[bl * 68 + k];
            float4 w01 = *reinterpret_cast<const float4*>(ws + k * 64 + cg * 8);
            float4 w23 = *reinterpret_cast<const float4*>(ws + k * 64 + cg * 8 + 4);
            acc[0] += qv * w01.x; acc[1] += qv * w01.y;
            acc[2] += qv * w01.z; acc[3] += qv * w01.w;
            acc[4] += qv * w23.x; acc[5] += qv * w23.y;
            acc[6] += qv * w23.z; acc[7] += qv * w23.w;
        }
    }
    int bglob = bg * 32 + bl;
#pragma unroll
    for (int j = 0; j < 8; ++j) {
        int c = cg * 8 + j;
        g_fq[bglob * 256 + h * 64 + c] = silu_f(acc[j] + g_bq[h * DD2 + c]);
    }
}

// ---------------- fused main kernel: one block per (b,h), 2 CTAs/SM ----------------
// 8 warps: ch = w&1 (col half, 64 cols), wr = w>>1.
// Lane: gg = wr*2 + (lane>>4) (10-row group), cg = lane&15 -> 4 cols.
// 3 passes of 80/80/40 rows. fdT[k][80]: 8 groups x 10 rows, transposed, stride 80.
// merge arrays mo/mp/mSs OVERLAY fdT (dead after mainloop).
#define OFF_FDT  16384
#define OFF_LG   (OFF_FDT + 10240)
#define SMEM_FLOATS (OFF_LG + 80)
#define SMEM_BYTES  (SMEM_FLOATS * 4)   // 106816 B -> 2 CTAs/SM

__global__ __launch_bounds__(256, 2) void mha_main_kernel(
    const float* __restrict__ fact,
    const int* __restrict__ mask, const float* __restrict__ mm,
    const float* __restrict__ tau1, const float* __restrict__ tau2,
    float* __restrict__ out)
{
    extern __shared__ float sm[];
    float* W_s  = sm;              // [128 k][128 c]
    float* fdT  = sm + OFF_FDT;    // [128 k][80]
    float* lg_s = sm + OFF_LG;     // [80]
    float* mo   = sm + OFF_FDT;          // [8][64]  (overlay, used after loop)
    float* mp   = mo + 512;               // [8][64]
    float* mSs  = mp + 512;               // [16]

    const int tid = threadIdx.x;
    const int b = blockIdx.x >> 2;
    const int h = blockIdx.x & 3;
    const int w    = tid >> 5;
    const int lane = tid & 31;
    const int ch = w & 1;              // 0: f-cols, 1: v-cols
    const int wr = w >> 1;             // 0..3
    const int rg = lane >> 4;
    const int cg = lane & 15;
    const int gg = wr * 2 + rg;        // 0..7 (10 rows each)
    const int col = ch * 64 + cg * 4;  // 4 cols
    const bool is_f = (ch == 0);

    // staging identity
    const int sgg = lane >> 3;         // 0..3
    const int sks = (lane >> 1) & 3;   // 0..3
    const int sjh = lane & 1;          // 0..1

    // stage W
    {
        const float4* gw = reinterpret_cast<const float4*>(g_Wc + h * 16384);
        float4* ws4 = reinterpret_cast<float4*>(W_s);
#pragma unroll
        for (int i = 0; i < 16; ++i) ws4[tid + 256 * i] = gw[tid + 256 * i];
    }

    const float t1a = tau1[h], t1b = tau1[4 + h];
    const float cb1v = tau2[h], cb2v = tau2[4 + h], cb3v = tau2[8 + h];

    float4 bc4 = *reinterpret_cast<const float4*>(g_bc + h * 128 + col);
    float4 fq4 = make_float4(0.f, 0.f, 0.f, 0.f);
    if (is_f) fq4 = *reinterpret_cast<const float4*>(g_fq + b * 256 + h * 64 + col);

    const float4* fact4 = reinterpret_cast<const float4*>(fact + (long)b * 200 * 128);

    float m_run = -FLT_MAX, S_run = 0.f;
    float ov[4] = {0.f, 0.f, 0.f, 0.f}, pv[4] = {0.f, 0.f, 0.f, 0.f};

#pragma unroll 1
    for (int t = 0; t < 3; ++t) {
        const int tb = t * 80;
        __syncthreads();   // fdT(t-1) + lg(t-1) fully consumed
        // ---- stage 80-row transposed tile (zero-pad rows >= 200) ----
        const int kb = 16 * w + 4 * sks;
#pragma unroll
        for (int g2 = 0; g2 < 2; ++g2) {
#pragma unroll
            for (int jj = 0; jj < 5; ++jj) {
                int j5 = jj + sks; if (j5 >= 5) j5 -= 5;
                int j = 5 * sjh + j5;
                int grp = sgg + 4 * g2;
                int lrow = tb + 10 * grp + j;
                float4 f = (lrow < 200) ? fact4[lrow * 32 + 4 * w + sks]
                                        : make_float4(0.f, 0.f, 0.f, 0.f);
                float* d = fdT + 10 * grp + j;
                d[(kb + 0) * 80] = f.x;
                d[(kb + 1) * 80] = f.y;
                d[(kb + 2) * 80] = f.z;
                d[(kb + 3) * 80] = f.w;
            }
        }
        __syncthreads();

        // ---- mainloop: 5 row-pairs x 4 cols per lane ----
        unsigned long long a0[5], a1[5], a2[5], a3[5];
#pragma unroll
        for (int p = 0; p < 5; ++p) { a0[p] = 0ull; a1[p] = 0ull; a2[p] = 0ull; a3[p] = 0ull; }
        {
            const float* ap = fdT + 10 * gg;
            const float* wp = W_s + col;
#pragma unroll 4
            for (int k = 0; k < 128; ++k) {
                unsigned long long f0 = *reinterpret_cast<const unsigned long long*>(ap);
                unsigned long long f1 = *reinterpret_cast<const unsigned long long*>(ap + 2);
                unsigned long long f2 = *reinterpret_cast<const unsigned long long*>(ap + 4);
                unsigned long long f3 = *reinterpret_cast<const unsigned long long*>(ap + 6);
                unsigned long long f4 = *reinterpret_cast<const unsigned long long*>(ap + 8);
                float4 wv = *reinterpret_cast<const float4*>(wp);
                unsigned long long w0 = dup2(wv.x), w1 = dup2(wv.y);
                unsigned long long w2 = dup2(wv.z), w3 = dup2(wv.w);
                ffma2(a0[0], f0, w0); ffma2(a1[0], f0, w1); ffma2(a2[0], f0, w2); ffma2(a3[0], f0, w3);
                ffma2(a0[1], f1, w0); ffma2(a1[1], f1, w1); ffma2(a2[1], f1, w2); ffma2(a3[1], f1, w3);
                ffma2(a0[2], f2, w0); ffma2(a1[2], f2, w1); ffma2(a2[2], f2, w2); ffma2(a3[2], f2, w3);
                ffma2(a0[3], f3, w0); ffma2(a1[3], f3, w1); ffma2(a2[3], f3, w2); ffma2(a3[3], f3, w3);
                ffma2(a0[4], f4, w0); ffma2(a1[4], f4, w1); ffma2(a2[4], f4, w2); ffma2(a3[4], f4, w3);
                ap += 80; wp += 128;
            }
        }

        // ---- epilogue ----
        float sv[10][4];
#pragma unroll
        for (int p = 0; p < 5; ++p) {
            float2 c0 = unpk(a0[p]), c1 = unpk(a1[p]);
            float2 c2 = unpk(a2[p]), c3 = unpk(a3[p]);
            sv[2*p][0]   = silu_f(c0.x + bc4.x); sv[2*p][1]   = silu_f(c1.x + bc4.y);
            sv[2*p][2]   = silu_f(c2.x + bc4.z); sv[2*p][3]   = silu_f(c3.x + bc4.w);
            sv[2*p+1][0] = silu_f(c0.y + bc4.x); sv[2*p+1][1] = silu_f(c1.y + bc4.y);
            sv[2*p+1][2] = silu_f(c2.y + bc4.z); sv[2*p+1][3] = silu_f(c3.y + bc4.w);
        }
        if (is_f) {
            float pd[10];
#pragma unroll
            for (int j = 0; j < 10; ++j) {
                pd[j] = sv[j][0] * fq4.x + sv[j][1] * fq4.y + sv[j][2] * fq4.z + sv[j][3] * fq4.w;
#pragma unroll
                for (int off = 8; off > 0; off >>= 1)
                    pd[j] += __shfl_xor_sync(0xffffffffu, pd[j], off);
            }
            float mine = pd[0];
#pragma unroll
            for (int j = 1; j < 10; ++j)
                if (cg == j) mine = pd[j];
            int l = tb + gg * 10 + cg;
            if (cg < 10 && l < 200) {
                float mk = (float)mask[b * 200 + l];
                float dd = mine + (-1e9f) * (1.f - mk);   // mask BEFORE cosine mix
                float bias = mm[b * 200 + l] / t1a + mm[204800 + b * 200 + l] / t1b;
                lg_s[gg * 10 + cg] = cb1v * dd + cb2v * bias + cb3v * dd * bias;
            }
        }
        __syncthreads();   // lg_s(t) visible; fdT(t) consumed

        if (!is_f && (t < 2 || gg < 4)) {
#pragma unroll
            for (int j = 0; j < 10; ++j) {
                float lgv = lg_s[gg * 10 + j];
                float mn = fmaxf(m_run, lgv);
                float sc = __expf(m_run - mn);
                float e  = __expf(lgv - mn);
                S_run = S_run * sc + e;
#pragma unroll
                for (int c = 0; c < 4; ++c) {
                    ov[c] = ov[c] * sc + e * sv[j][c];
                    pv[c] += sv[j][c];
                }
                m_run = mn;
            }
        }
    }
    __syncthreads();   // everyone past all fdT reads; safe to overlay merge arrays

    // ---- merge 8 row-groups (mo/mp/mSs overlay fdT) ----
    if (!is_f) {
        int cv = col - 64;
#pragma unroll
        for (int c = 0; c < 4; ++c) {
            mo[gg * 64 + cv + c] = ov[c];
            mp[gg * 64 + cv + c] = pv[c];
        }
        if (cg == 0) { mSs[gg] = m_run; mSs[8 + gg] = S_run; }
    }
    __syncthreads();

    if (tid < 64) {
        float M = -FLT_MAX;
#pragma unroll
        for (int g = 0; g < 8; ++g) M = fmaxf(M, mSs[g]);
        float S = 0.f, o = 0.f, p = 0.f;
#pragma unroll
        for (int g = 0; g < 8; ++g) {
            float e = __expf(mSs[g] - M);
            S += mSs[8 + g] * e;
            o += mo[g * 64 + tid] * e;
            p += mp[g * 64 + tid];
        }
        out[b * 256 + h * 64 + tid] = o / S + 1e-7f * p;
    }
}

extern "C" void kernel_launch(void* const* d_in, const int* in_sizes, int n_in,
                              void* d_out, int out_size) {
    const float* query = (const float*)d_in[0];
    const float* fact  = (const float*)d_in[1];
    const int*   mask  = (const int*)  d_in[2];
    const float* mm    = (const float*)d_in[3];
    const float* Wq1   = (const float*)d_in[4];
    const float* bq1   = (const float*)d_in[5];
    const float* Wq2   = (const float*)d_in[6];
    const float* bq2   = (const float*)d_in[7];
    const float* Wf1   = (const float*)d_in[8];
    const float* bf1   = (const float*)d_in[9];
    const float* Wf2   = (const float*)d_in[10];
    const float* bf2   = (const float*)d_in[11];
    const float* Wv1   = (const float*)d_in[12];
    const float* bv1   = (const float*)d_in[13];
    const float* Wv2   = (const float*)d_in[14];
    const float* bv2   = (const float*)d_in[15];
    const float* tau1  = (const float*)d_in[16];
    const float* tau2  = (const float*)d_in[17];
    float* out = (float*)d_out;

    cudaFuncSetAttribute(mha_main_kernel, cudaFuncAttributeMaxDynamicSharedMemorySize, SMEM_BYTES);

    collapse_q_kernel<<<512, 256>>>(Wq1, bq1, Wq2, bq2);
    collapse_fv_kernel<<<256, 256>>>(Wf1, bf1, Wf2, bf2, Wv1, bv1, Wv2, bv2);
    fq_kernel<<<128, 256>>>(query);
    mha_main_kernel<<<BB * HH, 256, SMEM_BYTES>>>(fact, mask, mm, tau1, tau2, out);
}

// round 9
// speedup vs baseline: 1.5436x; 1.3142x over previous
#include <cuda_runtime.h>
#include <cuda_bf16.h>
#include <float.h>
#include <stdint.h>

#define HH 4
#define BB 1024
#define DQv 512
#define DFv 128
#define DD1 128
#define DD2 64

__device__ float g_Wq[HH * DQv * DD2];
__device__ float g_bq[HH * DD2];
__device__ float g_WcT[HH * 128 * 128];   // [h][c][k]
__device__ float g_bc[HH * 128];
__device__ float g_fq[BB * HH * DD2];

__device__ __forceinline__ float silu_f(float x) { return __fdividef(x, 1.f + __expf(-x)); }
__device__ __forceinline__ uint32_t smem_u32(const void* p) {
    uint32_t a;
    asm("{ .reg .u64 t; cvta.to.shared.u64 t, %1; cvt.u32.u64 %0, t; }" : "=r"(a) : "l"(p));
    return a;
}
__device__ __forceinline__ uint32_t bf2pack(float lo, float hi) {
    uint32_t r;
    asm("cvt.rn.bf16x2.f32 %0, %1, %2;" : "=r"(r) : "f"(hi), "f"(lo));
    return r;
}
__device__ __forceinline__ float bflo(uint32_t q) { return __uint_as_float(q << 16); }
__device__ __forceinline__ float bfhi(uint32_t q) { return __uint_as_float(q & 0xffff0000u); }

__device__ __forceinline__ void split3(const float* x, uint4& o0, uint4& o1, uint4& o2) {
    uint32_t p0[4], p1[4], p2[4];
#pragma unroll
    for (int i = 0; i < 4; ++i) {
        float lo = x[2 * i], hi = x[2 * i + 1];
        uint32_t q0 = bf2pack(lo, hi);
        float rlo = lo - bflo(q0), rhi = hi - bfhi(q0);
        uint32_t q1 = bf2pack(rlo, rhi);
        float slo = rlo - bflo(q1), shi = rhi - bfhi(q1);
        uint32_t q2 = bf2pack(slo, shi);
        p0[i] = q0; p1[i] = q1; p2[i] = q2;
    }
    o0 = make_uint4(p0[0], p0[1], p0[2], p0[3]);
    o1 = make_uint4(p1[0], p1[1], p1[2], p1[3]);
    o2 = make_uint4(p2[0], p2[1], p2[2], p2[3]);
}

__device__ __forceinline__ void ldm_x4(uint32_t a[4], uint32_t addr) {
    asm volatile("ldmatrix.sync.aligned.m8n8.x4.shared.b16 {%0,%1,%2,%3}, [%4];"
        : "=r"(a[0]), "=r"(a[1]), "=r"(a[2]), "=r"(a[3]) : "r"(addr));
}
__device__ __forceinline__ void ldm_x2(uint32_t b[2], uint32_t addr) {
    asm volatile("ldmatrix.sync.aligned.m8n8.x2.shared.b16 {%0,%1}, [%2];"
        : "=r"(b[0]), "=r"(b[1]) : "r"(addr));
}
__device__ __forceinline__ void mma16816(float d[4], const uint32_t a[4], const uint32_t b[2]) {
    asm volatile(
        "mma.sync.aligned.m16n8k16.row.col.f32.bf16.bf16.f32 "
        "{%0,%1,%2,%3}, {%4,%5,%6,%7}, {%8,%9}, {%0,%1,%2,%3};"
        : "+f"(d[0]), "+f"(d[1]), "+f"(d[2]), "+f"(d[3])
        : "r"(a[0]), "r"(a[1]), "r"(a[2]), "r"(a[3]), "r"(b[0]), "r"(b[1]));
}

// ---------------- prekernels (proven) ----------------
__global__ void collapse_q_kernel(const float* __restrict__ Wq1, const float* __restrict__ bq1,
                                  const float* __restrict__ Wq2, const float* __restrict__ bq2) {
    int idx = blockIdx.x * 256 + threadIdx.x;
    int c = idx & 63, k = (idx >> 6) & 511, h = idx >> 15;
    const float* a  = Wq1 + (h * DQv + k) * DD1;
    const float* w2 = Wq2 + h * DD1 * DD2 + c;
    float acc = 0.f;
#pragma unroll 8
    for (int j = 0; j < DD1; ++j) acc += a[j] * w2[j * DD2];
    g_Wq[idx] = acc;
    if (k == 0) {
        float bb = bq2[h * DD2 + c];
        const float* b1p = bq1 + h * DD1;
#pragma unroll 8
        for (int j = 0; j < DD1; ++j) bb += b1p[j] * w2[j * DD2];
        g_bq[h * DD2 + c] = bb;
    }
}

__global__ void collapse_fvT_kernel(const float* __restrict__ Wf1, const float* __restrict__ bf1,
                                    const float* __restrict__ Wf2, const float* __restrict__ bf2,
                                    const float* __restrict__ Wv1, const float* __restrict__ bv1,
                                    const float* __restrict__ Wv2, const float* __restrict__ bv2) {
    int idx = blockIdx.x * 256 + threadIdx.x;
    int c = idx & 127, k = (idx >> 7) & 127, h = idx >> 14;
    const float *W1, *W2, *B1, *B2; int cc;
    if (c < 64) { W1 = Wf1; W2 = Wf2; B1 = bf1; B2 = bf2; cc = c; }
    else        { W1 = Wv1; W2 = Wv2; B1 = bv1; B2 = bv2; cc = c - 64; }
    const float* a  = W1 + (h * DFv + k) * DD1;
    const float* w2 = W2 + h * DD1 * DD2 + cc;
    float acc = 0.f;
#pragma unroll 8
    for (int j = 0; j < DD1; ++j) acc += a[j] * w2[j * DD2];
    g_WcT[h * 16384 + c * 128 + k] = acc;
    if (k == 0) {
        float bb = B2[h * DD2 + cc];
        const float* b1p = B1 + h * DD1;
#pragma unroll 8
        for (int j = 0; j < DD1; ++j) bb += b1p[j] * w2[j * DD2];
        g_bc[h * 128 + c] = bb;
    }
}

__global__ __launch_bounds__(256) void fq_kernel(const float* __restrict__ query) {
    __shared__ float qs[32 * 68];
    __shared__ float ws[64 * 64];
    const int tid = threadIdx.x;
    const int h  = blockIdx.x & 3;
    const int bg = blockIdx.x >> 2;
    const int bl = tid >> 3, cg = tid & 7;
    float acc[8];
#pragma unroll
    for (int j = 0; j < 8; ++j) acc[j] = 0.f;
    for (int kc = 0; kc < 8; ++kc) {
        __syncthreads();
#pragma unroll
        for (int it = 0; it < 8; ++it) {
            int idx = tid + it * 256;
            qs[(idx >> 6) * 68 + (idx & 63)] = query[(bg * 32 + (idx >> 6)) * DQv + kc * 64 + (idx & 63)];
        }
#pragma unroll
        for (int it = 0; it < 16; ++it) {
            int idx = tid + it * 256;
            ws[idx] = g_Wq[(h * DQv + kc * 64 + (idx >> 6)) * DD2 + (idx & 63)];
        }
        __syncthreads();
#pragma unroll 4
        for (int k = 0; k < 64; ++k) {
            float qv = qs[bl * 68 + k];
            float4 w01 = *reinterpret_cast<const float4*>(ws + k * 64 + cg * 8);
            float4 w23 = *reinterpret_cast<const float4*>(ws + k * 64 + cg * 8 + 4);
            acc[0] += qv * w01.x; acc[1] += qv * w01.y;
            acc[2] += qv * w01.z; acc[3] += qv * w01.w;
            acc[4] += qv * w23.x; acc[5] += qv * w23.y;
            acc[6] += qv * w23.z; acc[7] += qv * w23.w;
        }
    }
    int bglob = bg * 32 + bl;
#pragma unroll
    for (int j = 0; j < 8; ++j) {
        int c = cg * 8 + j;
        g_fq[bglob * 256 + h * 64 + c] = silu_f(acc[j] + g_bq[h * DD2 + c]);
    }
}

// ---------------- HMMA main kernel: one CTA per (b,h) ----------------
// smem: as[3][112][136]bf16 | bs[3][128][136]bf16 | pdw[4][224] | alf[224] | msc[32]
#define AS_SPL 30464
#define BS_OFF 91392
#define BS_SPL 34816
#define SCR_OFF 195840
#define SMEM_BYTES 200448

template<int MT>
__device__ __forceinline__ void gemm_half(uint32_t sbase, int nb, int lane, float d[][8]) {
#pragma unroll
    for (int mt = 0; mt < MT; ++mt)
#pragma unroll
        for (int i = 0; i < 8; ++i) d[mt][i] = 0.f;

    const uint32_t arow = (uint32_t)((lane & 15) * 136 + (lane >> 4) * 8) * 2;
    const uint32_t brow = (uint32_t)((nb + (lane & 7)) * 136 + ((lane >> 3) & 1) * 8) * 2;

#pragma unroll 1
    for (int ks = 0; ks < 8; ++ks) {
        const uint32_t kso = (uint32_t)(ks * 16) * 2;
        uint32_t bf[3][2][2];
#pragma unroll
        for (int s = 0; s < 3; ++s) {
            ldm_x2(bf[s][0], sbase + BS_OFF + s * BS_SPL + brow + kso);
            ldm_x2(bf[s][1], sbase + BS_OFF + s * BS_SPL + brow + kso + (uint32_t)(8 * 136) * 2);
        }
#pragma unroll
        for (int mt = 0; mt < MT; ++mt) {
            const uint32_t aoff = arow + kso + (uint32_t)(mt * 16 * 136) * 2;
            uint32_t a0[4], a1[4], a2[4];
            ldm_x4(a0, sbase + aoff);
            ldm_x4(a1, sbase + AS_SPL + aoff);
            ldm_x4(a2, sbase + 2 * AS_SPL + aoff);
            // 6 split-pairs into one accumulator, both n8 halves
            mma16816(d[mt],     a0, bf[0][0]); mma16816(d[mt] + 4, a0, bf[0][1]);
            mma16816(d[mt],     a0, bf[1][0]); mma16816(d[mt] + 4, a0, bf[1][1]);
            mma16816(d[mt],     a0, bf[2][0]); mma16816(d[mt] + 4, a0, bf[2][1]);
            mma16816(d[mt],     a1, bf[0][0]); mma16816(d[mt] + 4, a1, bf[0][1]);
            mma16816(d[mt],     a1, bf[1][0]); mma16816(d[mt] + 4, a1, bf[1][1]);
            mma16816(d[mt],     a2, bf[0][0]); mma16816(d[mt] + 4, a2, bf[0][1]);
        }
    }
}

__global__ __launch_bounds__(256, 1) void mha_hmma_kernel(
    const float* __restrict__ fact,
    const int* __restrict__ mask, const float* __restrict__ mm,
    const float* __restrict__ tau1, const float* __restrict__ tau2,
    float* __restrict__ out)
{
    extern __shared__ char smem[];
    float* pdw = reinterpret_cast<float*>(smem + SCR_OFF);  // [4][224]
    float* alf = pdw + 4 * 224;                             // [224]
    float* msc = alf + 224;                                 // [32]

    const int tid  = threadIdx.x;
    const int w    = tid >> 5;
    const int lane = tid & 31;
    const int g    = lane >> 2;
    const int t4   = lane & 3;
    const int b = blockIdx.x >> 2;
    const int h = blockIdx.x & 3;
    const int nb = w * 16;            // warp's 16 cols
    const bool is_f = (w < 4);
    const uint32_t sbase = smem_u32(smem);

    // thread's 4 columns
    const int c0 = nb + t4 * 2, c1 = c0 + 1, c2 = c0 + 8, c3 = c0 + 9;
    const float bc0 = g_bc[h * 128 + c0], bc1 = g_bc[h * 128 + c1];
    const float bc2 = g_bc[h * 128 + c2], bc3 = g_bc[h * 128 + c3];
    float fq0 = 0.f, fq1 = 0.f, fq2 = 0.f, fq3 = 0.f;
    if (is_f) {
        fq0 = g_fq[b * 256 + h * 64 + c0]; fq1 = g_fq[b * 256 + h * 64 + c1];
        fq2 = g_fq[b * 256 + h * 64 + c2]; fq3 = g_fq[b * 256 + h * 64 + c3];
    }

    // ---- stage B splits (once) ----
#pragma unroll
    for (int it = 0; it < 8; ++it) {
        int idx = tid + it * 256;          // 2048
        int c = idx >> 4, k8 = idx & 15;
        const float* src = g_WcT + h * 16384 + c * 128 + k8 * 8;
        float xv[8];
        *reinterpret_cast<float4*>(xv)     = *reinterpret_cast<const float4*>(src);
        *reinterpret_cast<float4*>(xv + 4) = *reinterpret_cast<const float4*>(src + 4);
        uint4 o0, o1, o2;
        split3(xv, o0, o1, o2);
        uint32_t byte = (uint32_t)(c * 272 + k8 * 16);
        *reinterpret_cast<uint4*>(smem + BS_OFF + byte)              = o0;
        *reinterpret_cast<uint4*>(smem + BS_OFF + BS_SPL + byte)     = o1;
        *reinterpret_cast<uint4*>(smem + BS_OFF + 2 * BS_SPL + byte) = o2;
    }

    // ---- stage A half0 (rows 0..111) ----
#pragma unroll
    for (int it = 0; it < 7; ++it) {
        int idx = tid + it * 256;          // 1792
        int l = idx >> 4, k8 = idx & 15;
        const float* src = fact + ((long)b * 200 + l) * 128 + k8 * 8;
        float xv[8];
        *reinterpret_cast<float4*>(xv)     = *reinterpret_cast<const float4*>(src);
        *reinterpret_cast<float4*>(xv + 4) = *reinterpret_cast<const float4*>(src + 4);
        uint4 o0, o1, o2;
        split3(xv, o0, o1, o2);
        uint32_t byte = (uint32_t)(l * 272 + k8 * 16);
        *reinterpret_cast<uint4*>(smem + byte)              = o0;
        *reinterpret_cast<uint4*>(smem + AS_SPL + byte)     = o1;
        *reinterpret_cast<uint4*>(smem + 2 * AS_SPL + byte) = o2;
    }
    __syncthreads();

    // ---- half0 GEMM ----
    float d0[7][8];
    gemm_half<7>(sbase, nb, lane, d0);

    // f-warps fold dot for half0 rows
    if (is_f) {
#pragma unroll
        for (int mt = 0; mt < 7; ++mt) {
            float s0 = silu_f(d0[mt][0] + bc0) * fq0 + silu_f(d0[mt][1] + bc1) * fq1
                     + silu_f(d0[mt][4] + bc2) * fq2 + silu_f(d0[mt][5] + bc3) * fq3;
            float s1 = silu_f(d0[mt][2] + bc0) * fq0 + silu_f(d0[mt][3] + bc1) * fq1
                     + silu_f(d0[mt][6] + bc2) * fq2 + silu_f(d0[mt][7] + bc3) * fq3;
            s0 += __shfl_xor_sync(0xffffffffu, s0, 1); s0 += __shfl_xor_sync(0xffffffffu, s0, 2);
            s1 += __shfl_xor_sync(0xffffffffu, s1, 1); s1 += __shfl_xor_sync(0xffffffffu, s1, 2);
            if (t4 == 0) {
                pdw[w * 224 + mt * 16 + g]     = s0;
                pdw[w * 224 + mt * 16 + g + 8] = s1;
            }
        }
    }
    __syncthreads();   // half0 A reads done

    // ---- stage A half1 (rows 112..207, pad >=200 zero) ----
#pragma unroll
    for (int it = 0; it < 6; ++it) {
        int idx = tid + it * 256;          // 1536
        int l = idx >> 4, k8 = idx & 15;
        int lg = 112 + l;
        float xv[8];
        if (lg < 200) {
            const float* src = fact + ((long)b * 200 + lg) * 128 + k8 * 8;
            *reinterpret_cast<float4*>(xv)     = *reinterpret_cast<const float4*>(src);
            *reinterpret_cast<float4*>(xv + 4) = *reinterpret_cast<const float4*>(src + 4);
        } else {
#pragma unroll
            for (int e = 0; e < 8; ++e) xv[e] = 0.f;
        }
        uint4 o0, o1, o2;
        split3(xv, o0, o1, o2);
        uint32_t byte = (uint32_t)(l * 272 + k8 * 16);
        *reinterpret_cast<uint4*>(smem + byte)              = o0;
        *reinterpret_cast<uint4*>(smem + AS_SPL + byte)     = o1;
        *reinterpret_cast<uint4*>(smem + 2 * AS_SPL + byte) = o2;
    }
    __syncthreads();

    // ---- half1 GEMM ----
    float d1[6][8];
    gemm_half<6>(sbase, nb, lane, d1);

    if (is_f) {
#pragma unroll
        for (int mt = 0; mt < 6; ++mt) {
            float s0 = silu_f(d1[mt][0] + bc0) * fq0 + silu_f(d1[mt][1] + bc1) * fq1
                     + silu_f(d1[mt][4] + bc2) * fq2 + silu_f(d1[mt][5] + bc3) * fq3;
            float s1 = silu_f(d1[mt][2] + bc0) * fq0 + silu_f(d1[mt][3] + bc1) * fq1
                     + silu_f(d1[mt][6] + bc2) * fq2 + silu_f(d1[mt][7] + bc3) * fq3;
            s0 += __shfl_xor_sync(0xffffffffu, s0, 1); s0 += __shfl_xor_sync(0xffffffffu, s0, 2);
            s1 += __shfl_xor_sync(0xffffffffu, s1, 1); s1 += __shfl_xor_sync(0xffffffffu, s1, 2);
            if (t4 == 0) {
                pdw[w * 224 + 112 + mt * 16 + g]     = s0;
                pdw[w * 224 + 112 + mt * 16 + g + 8] = s1;
            }
        }
    }
    __syncthreads();

    // ---- logits ----
    const float t1a = tau1[h], t1b = tau1[4 + h];
    const float cb1v = tau2[h], cb2v = tau2[4 + h], cb3v = tau2[8 + h];
    if (tid < 200) {
        float dd = pdw[tid] + pdw[224 + tid] + pdw[448 + tid] + pdw[672 + tid];
        float mk = (float)mask[b * 200 + tid];
        dd += (-1e9f) * (1.f - mk);                 // mask BEFORE cosine mix
        float bias = mm[b * 200 + tid] / t1a + mm[204800 + b * 200 + tid] / t1b;
        alf[tid] = cb1v * dd + cb2v * bias + cb3v * dd * bias;
    }
    __syncthreads();

    // ---- softmax over 200 ----
    float v = (tid < 200) ? alf[tid] : -3.0e38f;
    float mxv = v;
#pragma unroll
    for (int off = 16; off > 0; off >>= 1) mxv = fmaxf(mxv, __shfl_xor_sync(0xffffffffu, mxv, off));
    if (lane == 0) msc[w] = mxv;
    __syncthreads();
    if (tid == 0) {
        float m = msc[0];
#pragma unroll
        for (int i = 1; i < 8; ++i) m = fmaxf(m, msc[i]);
        msc[8] = m;
    }
    __syncthreads();
    float e = (tid < 200) ? expf(v - msc[8]) : 0.f;
    float se = e;
#pragma unroll
    for (int off = 16; off > 0; off >>= 1) se += __shfl_xor_sync(0xffffffffu, se, off);
    if (lane == 0) msc[16 + w] = se;
    __syncthreads();
    if (tid == 0) {
        float s = 0.f;
#pragma unroll
        for (int i = 0; i < 8; ++i) s += msc[16 + i];
        msc[9] = __fdividef(1.f, s);
    }
    __syncthreads();
    if (tid < 200) alf[tid] = e * msc[9];
    __syncthreads();

    // ---- v-warps: alpha-weighted reduce + 1e-7 * plain sum ----
    if (!is_f) {
        float o[4] = {0.f, 0.f, 0.f, 0.f}, pp[4] = {0.f, 0.f, 0.f, 0.f};
#pragma unroll
        for (int mt = 0; mt < 7; ++mt) {
            int l0 = mt * 16 + g, l1 = l0 + 8;
            {
                float a = alf[l0];
                float s0 = silu_f(d0[mt][0] + bc0), s1 = silu_f(d0[mt][1] + bc1);
                float s2 = silu_f(d0[mt][4] + bc2), s3 = silu_f(d0[mt][5] + bc3);
                o[0] += a * s0; o[1] += a * s1; o[2] += a * s2; o[3] += a * s3;
                pp[0] += s0; pp[1] += s1; pp[2] += s2; pp[3] += s3;
            }
            {
                float a = alf[l1];
                float s0 = silu_f(d0[mt][2] + bc0), s1 = silu_f(d0[mt][3] + bc1);
                float s2 = silu_f(d0[mt][6] + bc2), s3 = silu_f(d0[mt][7] + bc3);
                o[0] += a * s0; o[1] += a * s1; o[2] += a * s2; o[3] += a * s3;
                pp[0] += s0; pp[1] += s1; pp[2] += s2; pp[3] += s3;
            }
        }
#pragma unroll
        for (int mt = 0; mt < 6; ++mt) {
            int l0 = 112 + mt * 16 + g, l1 = l0 + 8;
            if (l0 < 200) {
                float a = alf[l0];
                float s0 = silu_f(d1[mt][0] + bc0), s1 = silu_f(d1[mt][1] + bc1);
                float s2 = silu_f(d1[mt][4] + bc2), s3 = silu_f(d1[mt][5] + bc3);
                o[0] += a * s0; o[1] += a * s1; o[2] += a * s2; o[3] += a * s3;
                pp[0] += s0; pp[1] += s1; pp[2] += s2; pp[3] += s3;
            }
            if (l1 < 200) {
                float a = alf[l1];
                float s0 = silu_f(d1[mt][2] + bc0), s1 = silu_f(d1[mt][3] + bc1);
                float s2 = silu_f(d1[mt][6] + bc2), s3 = silu_f(d1[mt][7] + bc3);
                o[0] += a * s0; o[1] += a * s1; o[2] += a * s2; o[3] += a * s3;
                pp[0] += s0; pp[1] += s1; pp[2] += s2; pp[3] += s3;
            }
        }
#pragma unroll
        for (int i = 0; i < 4; ++i) {
#pragma unroll
            for (int off = 4; off < 32; off <<= 1) {
                o[i]  += __shfl_xor_sync(0xffffffffu, o[i],  off);
                pp[i] += __shfl_xor_sync(0xffffffffu, pp[i], off);
            }
        }
        if (lane < 4) {
            int cv = nb - 64 + lane * 2;
            out[b * 256 + h * 64 + cv]     = o[0] + 1e-7f * pp[0];
            out[b * 256 + h * 64 + cv + 1] = o[1] + 1e-7f * pp[1];
            out[b * 256 + h * 64 + cv + 8] = o[2] + 1e-7f * pp[2];
            out[b * 256 + h * 64 + cv + 9] = o[3] + 1e-7f * pp[3];
        }
    }
}

extern "C" void kernel_launch(void* const* d_in, const int* in_sizes, int n_in,
                              void* d_out, int out_size) {
    const float* query = (const float*)d_in[0];
    const float* fact  = (const float*)d_in[1];
    const int*   mask  = (const int*)  d_in[2];
    const float* mm    = (const float*)d_in[3];
    const float* Wq1   = (const float*)d_in[4];
    const float* bq1   = (const float*)d_in[5];
    const float* Wq2   = (const float*)d_in[6];
    const float* bq2   = (const float*)d_in[7];
    const float* Wf1   = (const float*)d_in[8];
    const float* bf1   = (const float*)d_in[9];
    const float* Wf2   = (const float*)d_in[10];
    const float* bf2   = (const float*)d_in[11];
    const float* Wv1   = (const float*)d_in[12];
    const float* bv1   = (const float*)d_in[13];
    const float* Wv2   = (const float*)d_in[14];
    const float* bv2   = (const float*)d_in[15];
    const float* tau1  = (const float*)d_in[16];
    const float* tau2  = (const float*)d_in[17];
    float* out = (float*)d_out;

    cudaFuncSetAttribute(mha_hmma_kernel, cudaFuncAttributeMaxDynamicSharedMemorySize, SMEM_BYTES);

    collapse_q_kernel<<<512, 256>>>(Wq1, bq1, Wq2, bq2);
    collapse_fvT_kernel<<<256, 256>>>(Wf1, bf1, Wf2, bf2, Wv1, bv1, Wv2, bv2);
    fq_kernel<<<128, 256>>>(query);
    mha_hmma_kernel<<<BB * HH, 256, SMEM_BYTES>>>(fact, mask, mm, tau1, tau2, out);
}